// round 12
// baseline (speedup 1.0000x reference)
#include <cuda_runtime.h>

#define N_  32
#define C_  3
#define H_  224
#define W_  224
#define T_  17
#define HW_ (H_ * W_)
#define TILE_O 32

#define TROWS 45
#define TSTR  52                     // floats per row (48 stored + 4 pad; mult of 4)
#define CH_STR (TROWS * TSTR)        // 2340 floats/channel -> 28,080 B total

// identical fp expression for corners and pixels -> exact monotone bbox
#define MAP_X(wf, hf) __fadd_rn(__fsub_rn(__fmul_rn(c,(wf)), __fmul_rn(s,(hf))), 111.5f)
#define MAP_Y(wf, hf) __fadd_rn(__fadd_rn(__fmul_rn(s,(wf)), __fmul_rn(c,(hf))), 111.5f)

__global__ __launch_bounds__(256, 8) void rot_tile_v11_kernel(
    const float* __restrict__ x,       // (N, C, H, W)
    const float* __restrict__ thetas,  // (N, T)
    float* __restrict__ out)           // (N, T, C, H, W)
{
    __shared__ float tile[C_ * CH_STR];   // 28,080 B

    const int nt  = blockIdx.y;
    const int n   = nt / T_;
    const int tid = threadIdx.x;
    const int tx0 = (blockIdx.x % 7) * TILE_O;
    const int ty0 = (blockIdx.x / 7) * TILE_O;

    float s, c;
    sincosf(thetas[nt], &s, &c);

    // ---- exact input bbox from tile corners ----
    const float wfa = (float)tx0 - 111.5f;
    const float wfb = (float)(tx0 + TILE_O - 1) - 111.5f;
    const float hfa = (float)ty0 - 111.5f;
    const float hfb = (float)(ty0 + TILE_O - 1) - 111.5f;

    const float min_ix = fminf(fminf(MAP_X(wfa,hfa), MAP_X(wfb,hfa)),
                               fminf(MAP_X(wfa,hfb), MAP_X(wfb,hfb)));
    const float min_iy = fminf(fminf(MAP_Y(wfa,hfa), MAP_Y(wfb,hfa)),
                               fminf(MAP_Y(wfa,hfb), MAP_Y(wfb,hfb)));
    const float max_ix = fmaxf(fmaxf(MAP_X(wfa,hfa), MAP_X(wfb,hfa)),
                               fmaxf(MAP_X(wfa,hfb), MAP_X(wfb,hfb)));
    const float max_iy = fmaxf(fmaxf(MAP_Y(wfa,hfa), MAP_Y(wfb,hfa)),
                               fmaxf(MAP_Y(wfa,hfb), MAP_Y(wfb,hfb)));

    const int gx0 = (int)floorf(min_ix);
    const int gy0 = (int)floorf(min_iy);
    const int gx1 = (int)floorf(max_ix);
    const int gy1 = (int)floorf(max_iy);
    const int a0  = gx0 & ~3;                 // 16B-aligned col origin

    const int rows_needed = min(gy1 + 2 - gy0, TROWS);
    const int ents_needed = min(gx1 + 2 - a0,  48);

    const bool interior = (gx0 >= 0) && (gy0 >= 0) &&
                          (gx1 + 1 <= W_ - 1) && (gy1 + 1 <= H_ - 1);

    const int img_base = (n * C_) * HW_;
    const int lane = tid & 31;
    const int warp = tid >> 5;

    // ---- fill: aligned float4 -> STS.128, scalar fallback only for edge lanes ----
    if (lane < ((ents_needed + 3) >> 2)) {
        const int cbase  = a0 + 4 * lane;
        const bool vec_ok = (cbase >= 0) && (cbase + 3 <= W_ - 1);
        const int c0 = min(max(cbase,     0), W_ - 1);
        const int c1 = min(max(cbase + 1, 0), W_ - 1);
        const int c2 = min(max(cbase + 2, 0), W_ - 1);
        const int c3 = min(max(cbase + 3, 0), W_ - 1);

        for (int r = warp; r < rows_needed; r += 8) {
            const int gr = min(max(gy0 + r, 0), H_ - 1);
            const float* src = x + img_base + gr * W_;
#pragma unroll
            for (int ch = 0; ch < C_; ch++) {
                const float* sc = src + ch * HW_;
                float4 v;
                if (vec_ok) {
                    v = *reinterpret_cast<const float4*>(sc + cbase);
                } else {
                    v.x = sc[c0]; v.y = sc[c1]; v.z = sc[c2]; v.w = sc[c3];
                }
                *reinterpret_cast<float4*>(tile + ch * CH_STR + r * TSTR + 4 * lane) = v;
            }
        }
    }
    __syncthreads();

    // ---- compute: warp = 16 cols x 4 rows patch; thread = col pair ----
    const int cp    = lane & 7;          // col-pair within warp (0..7)
    const int rsub  = lane >> 3;         // sub-row within warp (0..3)
    const int col   = (warp & 1) * 16 + cp * 2;        // 0..30
    const int rowb  = (warp >> 1) * 4 + rsub;          // 0..15

    const float wf0 = (float)(tx0 + col) - 111.5f;
    const unsigned obase = (unsigned)nt * (C_ * HW_)
                         + (unsigned)(ty0 + rowb) * W_ + (unsigned)(tx0 + col);

#pragma unroll
    for (int j = 0; j < 2; j++) {
        const int row = rowb + 16 * j;
        const float hf = (float)(ty0 + row) - 111.5f;

        const float ixa = MAP_X(wf0, hf);
        const float iya = MAP_Y(wf0, hf);
        const float ixb = __fadd_rn(ixa, c);
        const float iyb = __fadd_rn(iya, s);

        const float fxa = ixa - floorf(ixa);
        const float fya = iya - floorf(iya);
        const float fxb = ixb - floorf(ixb);
        const float fyb = iyb - floorf(iyb);
        const int ix0a = (int)floorf(ixa), iy0a = (int)floorf(iya);
        const int ix0b = (int)floorf(ixb), iy0b = (int)floorf(iyb);

        const float gxa = 1.0f - fxa, gya = 1.0f - fya;
        const float gxb = 1.0f - fxb, gyb = 1.0f - fyb;

        // bbox exactness -> tile addresses always in stored range
        const int aA = (iy0a - gy0) * TSTR + (ix0a - a0);
        const int aB = (iy0b - gy0) * TSTR + (ix0b - a0);

        float wA00, wA01, wA10, wA11, wB00, wB01, wB10, wB11;
        if (interior) {
            wA00 = gya * gxa; wA01 = gya * fxa; wA10 = fya * gxa; wA11 = fya * fxa;
            wB00 = gyb * gxb; wB01 = gyb * fxb; wB10 = fyb * gxb; wB11 = fyb * fxb;
        } else {
            const float vxa0 = (ix0a >= 0  && ix0a < W_)     ? 1.0f : 0.0f;
            const float vxa1 = (ix0a >= -1 && ix0a < W_ - 1) ? 1.0f : 0.0f;
            const float vya0 = (iy0a >= 0  && iy0a < H_)     ? 1.0f : 0.0f;
            const float vya1 = (iy0a >= -1 && iy0a < H_ - 1) ? 1.0f : 0.0f;
            const float vxb0 = (ix0b >= 0  && ix0b < W_)     ? 1.0f : 0.0f;
            const float vxb1 = (ix0b >= -1 && ix0b < W_ - 1) ? 1.0f : 0.0f;
            const float vyb0 = (iy0b >= 0  && iy0b < H_)     ? 1.0f : 0.0f;
            const float vyb1 = (iy0b >= -1 && iy0b < H_ - 1) ? 1.0f : 0.0f;
            wA00 = gya * gxa * (vya0 * vxa0); wA01 = gya * fxa * (vya0 * vxa1);
            wA10 = fya * gxa * (vya1 * vxa0); wA11 = fya * fxa * (vya1 * vxa1);
            wB00 = gyb * gxb * (vyb0 * vxb0); wB01 = gyb * fxb * (vyb0 * vxb1);
            wB10 = fyb * gxb * (vyb1 * vxb0); wB11 = fyb * fxb * (vyb1 * vxb1);
        }

        const unsigned ob = obase + (unsigned)(16 * j) * W_;

#pragma unroll
        for (int ch = 0; ch < C_; ch++) {
            const float* t = tile + ch * CH_STR;
            float2 r2;
            r2.x = t[aA]        * wA00 + t[aA + 1]        * wA01
                 + t[aA + TSTR] * wA10 + t[aA + TSTR + 1] * wA11;
            r2.y = t[aB]        * wB00 + t[aB + 1]        * wB01
                 + t[aB + TSTR] * wB10 + t[aB + TSTR + 1] * wB11;
            *reinterpret_cast<float2*>(out + ob + (unsigned)ch * HW_) = r2;
        }
    }
}

extern "C" void kernel_launch(void* const* d_in, const int* in_sizes, int n_in,
                              void* d_out, int out_size) {
    const float* x      = (const float*)d_in[0];
    const float* thetas = (const float*)d_in[1];
    float* out          = (float*)d_out;

    dim3 block(256);
    dim3 grid(7 * 7, N_ * T_);   // 49 tiles x 544 rotations
    rot_tile_v11_kernel<<<grid, block>>>(x, thetas, out);
}

// round 16
// speedup vs baseline: 1.7251x; 1.7251x over previous
#include <cuda_runtime.h>
#include <cstdint>

#define N_  32
#define C_  3
#define H_  224
#define W_  224
#define T_  17
#define HW_ (H_ * W_)
#define TILE_O 32

#define TROWS 45
#define TCOLS 48                    // floats per row = 192 B
#define CH_STR (TROWS * TCOLS)      // 2160 floats per channel
#define TILE_BYTES (C_ * CH_STR * 4)   // 25,920
#define ROW_BYTES (TCOLS * 4)          // 192

// identical fp expression for corners and pixels -> exact monotone bbox
#define MAP_X(wf, hf) __fadd_rn(__fsub_rn(__fmul_rn(c,(wf)), __fmul_rn(s,(hf))), 111.5f)
#define MAP_Y(wf, hf) __fadd_rn(__fadd_rn(__fmul_rn(s,(wf)), __fmul_rn(c,(hf))), 111.5f)

__device__ __forceinline__ uint32_t smem_u32(const void* p) {
    uint32_t a;
    asm("{ .reg .u64 t; cvta.to.shared.u64 t, %1; cvt.u32.u64 %0, t; }"
        : "=r"(a) : "l"(p));
    return a;
}

__global__ __launch_bounds__(256, 8) void rot_tile_v13_kernel(
    const float* __restrict__ x,       // (N, C, H, W)
    const float* __restrict__ thetas,  // (N, T)
    float* __restrict__ out)           // (N, T, C, H, W)
{
    __shared__ __align__(16) float tile[C_ * CH_STR];   // 25,920 B
    __shared__ __align__(8) unsigned long long mbar;

    const int nt  = blockIdx.y;
    const int n   = nt / T_;
    const int tid = threadIdx.x;
    const int tx0 = (blockIdx.x % 7) * TILE_O;
    const int ty0 = (blockIdx.x / 7) * TILE_O;

    float s, c;
    sincosf(thetas[nt], &s, &c);

    // ---- exact input bbox from tile corners ----
    const float wfa = (float)tx0 - 111.5f;
    const float wfb = (float)(tx0 + TILE_O - 1) - 111.5f;
    const float hfa = (float)ty0 - 111.5f;
    const float hfb = (float)(ty0 + TILE_O - 1) - 111.5f;

    const float min_ix = fminf(fminf(MAP_X(wfa,hfa), MAP_X(wfb,hfa)),
                               fminf(MAP_X(wfa,hfb), MAP_X(wfb,hfb)));
    const float min_iy = fminf(fminf(MAP_Y(wfa,hfa), MAP_Y(wfb,hfa)),
                               fminf(MAP_Y(wfa,hfb), MAP_Y(wfb,hfb)));
    const float max_ix = fmaxf(fmaxf(MAP_X(wfa,hfa), MAP_X(wfb,hfa)),
                               fmaxf(MAP_X(wfa,hfb), MAP_X(wfb,hfb)));
    const float max_iy = fmaxf(fmaxf(MAP_Y(wfa,hfa), MAP_Y(wfb,hfa)),
                               fmaxf(MAP_Y(wfa,hfb), MAP_Y(wfb,hfb)));

    const int gx0 = (int)floorf(min_ix);
    const int gy0 = (int)floorf(min_iy);
    const int gx1 = (int)floorf(max_ix);
    const int gy1 = (int)floorf(max_iy);
    const int a0  = gx0 & ~3;                 // 16B-aligned col origin

    const bool interior = (gx0 >= 0) && (gy0 >= 0) &&
                          (gx1 + 1 <= W_ - 1) && (gy1 + 1 <= H_ - 1);
    // bulk path ok whenever x-window is inside the image (y clamped per-row)
    const bool col_ok = (a0 >= 0) && (a0 + TCOLS - 1 <= W_ - 1);

    const int img_base = (n * C_) * HW_;

    if (col_ok) {
        // ---- bulk-async fill: one 192B cp.async.bulk per (row, channel) ----
        if (tid == 0) {
            asm volatile("mbarrier.init.shared.b64 [%0], %1;"
                         :: "r"(smem_u32(&mbar)), "r"(1) : "memory");
        }
        __syncthreads();
        if (tid == 0) {
            asm volatile("mbarrier.arrive.expect_tx.shared.b64 _, [%0], %1;"
                         :: "r"(smem_u32(&mbar)), "r"(TILE_BYTES) : "memory");
        }
        __syncthreads();   // expect_tx posted before any copy can complete

        if (tid < TROWS * C_) {
            const int r  = tid % TROWS;
            const int ch = tid / TROWS;
            const int gr = min(max(gy0 + r, 0), H_ - 1);
            const float* src = x + img_base + ch * HW_ + gr * W_ + a0;
            const uint32_t dst = smem_u32(tile + ch * CH_STR + r * TCOLS);
            asm volatile(
                "cp.async.bulk.shared::cta.global.mbarrier::complete_tx::bytes "
                "[%0], [%1], %2, [%3];"
                :: "r"(dst), "l"(src), "r"(ROW_BYTES), "r"(smem_u32(&mbar))
                : "memory");
        }
        // all threads wait for the fill
        {
            const uint32_t mb = smem_u32(&mbar);
            asm volatile(
                "{\n\t"
                ".reg .pred P;\n\t"
                "W_%=:\n\t"
                "mbarrier.try_wait.parity.acquire.cta.shared::cta.b64 P, [%0], 0, 0x989680;\n\t"
                "@P bra D_%=;\n\t"
                "bra W_%=;\n\t"
                "D_%=:\n\t"
                "}"
                :: "r"(mb) : "memory");
        }
    } else {
        // ---- scalar clamped fill (edge-column tiles only, ~14/49) ----
        const int lane = tid & 31;
        const int warp = tid >> 5;
        const int gc0 = min(max(a0 + lane,      0), W_ - 1);
        const int gc1 = min(max(a0 + lane + 32, 0), W_ - 1);
        const bool have2 = lane < (TCOLS - 32);
        for (int r = warp; r < TROWS; r += 8) {
            const int gr = min(max(gy0 + r, 0), H_ - 1);
            const float* src = x + img_base + gr * W_;
            float* dst = tile + r * TCOLS;
#pragma unroll
            for (int ch = 0; ch < C_; ch++) {
                dst[ch * CH_STR + lane] = __ldg(src + ch * HW_ + gc0);
                if (have2)
                    dst[ch * CH_STR + lane + 32] = __ldg(src + ch * HW_ + gc1);
            }
        }
        __syncthreads();
    }

    // ---- compute: thread = (row tid>>4, col pair), 2 row-steps (v6, unchanged) ----
    const int orow = tid >> 4;           // 0..15
    const int ocol = (tid & 15) * 2;     // 0..30

    const float wf0 = (float)(tx0 + ocol) - 111.5f;
    const unsigned obase = (unsigned)nt * (C_ * HW_)
                         + (unsigned)(ty0 + orow) * W_ + (unsigned)(tx0 + ocol);

#pragma unroll
    for (int j = 0; j < 2; j++) {
        const int row = orow + 16 * j;
        const float hf = (float)(ty0 + row) - 111.5f;

        const float ixa = MAP_X(wf0, hf);
        const float iya = MAP_Y(wf0, hf);
        const float ixb = __fadd_rn(ixa, c);
        const float iyb = __fadd_rn(iya, s);

        const float fxa = ixa - floorf(ixa);
        const float fya = iya - floorf(iya);
        const float fxb = ixb - floorf(ixb);
        const float fyb = iyb - floorf(iyb);
        const int ix0a = (int)floorf(ixa), iy0a = (int)floorf(iya);
        const int ix0b = (int)floorf(ixb), iy0b = (int)floorf(iyb);

        const float gxa = 1.0f - fxa, gya = 1.0f - fya;
        const float gxb = 1.0f - fxb, gyb = 1.0f - fyb;

        int aA, aB;
        float wA00, wA01, wA10, wA11, wB00, wB01, wB10, wB11;
        if (interior) {
            wA00 = gya * gxa; wA01 = gya * fxa; wA10 = fya * gxa; wA11 = fya * fxa;
            wB00 = gyb * gxb; wB01 = gyb * fxb; wB10 = fyb * gxb; wB11 = fyb * fxb;
            aA = (iy0a - gy0) * TCOLS + (ix0a - a0);
            aB = (iy0b - gy0) * TCOLS + (ix0b - a0);
        } else {
            const float vxa0 = (ix0a >= 0  && ix0a < W_)     ? 1.0f : 0.0f;
            const float vxa1 = (ix0a >= -1 && ix0a < W_ - 1) ? 1.0f : 0.0f;
            const float vya0 = (iy0a >= 0  && iy0a < H_)     ? 1.0f : 0.0f;
            const float vya1 = (iy0a >= -1 && iy0a < H_ - 1) ? 1.0f : 0.0f;
            const float vxb0 = (ix0b >= 0  && ix0b < W_)     ? 1.0f : 0.0f;
            const float vxb1 = (ix0b >= -1 && ix0b < W_ - 1) ? 1.0f : 0.0f;
            const float vyb0 = (iy0b >= 0  && iy0b < H_)     ? 1.0f : 0.0f;
            const float vyb1 = (iy0b >= -1 && iy0b < H_ - 1) ? 1.0f : 0.0f;
            wA00 = gya * gxa * (vya0 * vxa0); wA01 = gya * fxa * (vya0 * vxa1);
            wA10 = fya * gxa * (vya1 * vxa0); wA11 = fya * fxa * (vya1 * vxa1);
            wB00 = gyb * gxb * (vyb0 * vxb0); wB01 = gyb * fxb * (vyb0 * vxb1);
            wB10 = fyb * gxb * (vyb1 * vxb0); wB11 = fyb * fxb * (vyb1 * vxb1);
            aA = min(max(iy0a - gy0, 0), TROWS - 2) * TCOLS
               + min(max(ix0a - a0,  0), TCOLS - 2);
            aB = min(max(iy0b - gy0, 0), TROWS - 2) * TCOLS
               + min(max(ix0b - a0,  0), TCOLS - 2);
        }

        const unsigned ob = obase + (unsigned)(16 * j) * W_;

#pragma unroll
        for (int ch = 0; ch < C_; ch++) {
            const float* t = tile + ch * CH_STR;
            float2 r2;
            r2.x = t[aA]         * wA00 + t[aA + 1]         * wA01
                 + t[aA + TCOLS] * wA10 + t[aA + TCOLS + 1] * wA11;
            r2.y = t[aB]         * wB00 + t[aB + 1]         * wB01
                 + t[aB + TCOLS] * wB10 + t[aB + TCOLS + 1] * wB11;
            *reinterpret_cast<float2*>(out + ob + (unsigned)ch * HW_) = r2;
        }
    }
}

extern "C" void kernel_launch(void* const* d_in, const int* in_sizes, int n_in,
                              void* d_out, int out_size) {
    const float* x      = (const float*)d_in[0];
    const float* thetas = (const float*)d_in[1];
    float* out          = (float*)d_out;

    dim3 block(256);
    dim3 grid(7 * 7, N_ * T_);   // 49 tiles x 544 rotations
    rot_tile_v13_kernel<<<grid, block>>>(x, thetas, out);
}